// round 1
// baseline (speedup 1.0000x reference)
#include <cuda_runtime.h>
#include <cuda_bf16.h>
#include <cstdint>
#include <cstdio>

// Problem constants
#define BATCH 8192
#define D_IN  1024
#define NH    2048
#define KLR   4
#define NCLS  1000
#define BN_EPS 1e-5f
#define NSEG  32

// ---------------- static device scratch (no allocations allowed) ----------------
__device__ float g_S[(size_t)BATCH * NH];          // 64MB  S = A @ mu^T
__device__ float g_P[(size_t)BATCH * NH * KLR];    // 256MB P = A @ V^T
__device__ float g_t[(size_t)BATCH * NH];          // pre-BN activations
__device__ float g_feat[(size_t)BATCH * NH];       // feat1 / feat2
__device__ float g_rowsq[BATCH];
__device__ float g_msq[NH];
__device__ float g_c[NH * KLR];
__device__ float g_mean[NH];
__device__ float g_scale[NH];
__device__ float g_shift[NH];
__device__ float g_psum[NSEG * NH];
__device__ float g_psq[NSEG * NH];

// ---------------- row sum of squares: out[b] = sum_d x[b,d]^2 ----------------
__global__ void rowsq_kernel(const float* __restrict__ x, float* __restrict__ out, int D) {
    int b = blockIdx.x;
    const float* p = x + (size_t)b * D;
    float s = 0.f;
    for (int i = threadIdx.x; i < D; i += 256) { float v = p[i]; s = fmaf(v, v, s); }
    __shared__ float red[256];
    red[threadIdx.x] = s;
    __syncthreads();
    for (int off = 128; off > 0; off >>= 1) {
        if (threadIdx.x < off) red[threadIdx.x] += red[threadIdx.x + off];
        __syncthreads();
    }
    if (threadIdx.x == 0) out[b] = red[0];
}

// ---------------- per-n constants: msq[n]=||mu_n||^2, c[n,k]=mu_n.v_{n,k} ------
__global__ void prep_kernel(const float* __restrict__ mu, const float* __restrict__ v,
                            float* __restrict__ msq, float* __restrict__ c, int D) {
    int n = blockIdx.x;
    const float* mp = mu + (size_t)n * D;
    const float* vp = v + (size_t)n * KLR * D;
    float acc[5] = {0.f, 0.f, 0.f, 0.f, 0.f};
    for (int i = threadIdx.x; i < D; i += 256) {
        float m = mp[i];
        acc[0] = fmaf(m, m, acc[0]);
        acc[1] = fmaf(m, vp[i], acc[1]);
        acc[2] = fmaf(m, vp[(size_t)D + i], acc[2]);
        acc[3] = fmaf(m, vp[(size_t)2 * D + i], acc[3]);
        acc[4] = fmaf(m, vp[(size_t)3 * D + i], acc[4]);
    }
    __shared__ float red[256];
    for (int j = 0; j < 5; j++) {
        red[threadIdx.x] = acc[j];
        __syncthreads();
        for (int off = 128; off > 0; off >>= 1) {
            if (threadIdx.x < off) red[threadIdx.x] += red[threadIdx.x + off];
            __syncthreads();
        }
        if (threadIdx.x == 0) {
            if (j == 0) msq[n] = red[0];
            else        c[n * KLR + (j - 1)] = red[0];
        }
        __syncthreads();
    }
}

// ---------------- SGEMM (NT): C[m,n] = sum_d A[m,d]*B[n,d] (+ bias[n]) ---------
// A: (M,Kd) row-major, B: (N,Kd) row-major. M % 128 == 0, Kd % 16 == 0.
#define BM 128
#define BN 128
#define BK 16
#define TM 8
#define TN 8
__global__ void __launch_bounds__(256)
sgemm_nt(const float* __restrict__ A, const float* __restrict__ Bm,
         float* __restrict__ C, int M, int N, int Kd, const float* __restrict__ bias) {
    __shared__ float As[BK][BM];
    __shared__ float Bs[BK][BN];
    const int tid = threadIdx.x;
    const int tx = tid % 16;        // n micro-tile
    const int ty = tid / 16;        // m micro-tile
    const int row0 = blockIdx.y * BM;
    const int col0 = blockIdx.x * BN;
    const int lrow = tid / 4;            // 0..63
    const int lcol = (tid % 4) * 4;      // 0,4,8,12

    float acc[TM][TN];
#pragma unroll
    for (int i = 0; i < TM; i++)
#pragma unroll
        for (int j = 0; j < TN; j++) acc[i][j] = 0.f;

    for (int k0 = 0; k0 < Kd; k0 += BK) {
#pragma unroll
        for (int r = 0; r < 2; r++) {
            int m = lrow + r * 64;
            float4 av = *(const float4*)(A + (size_t)(row0 + m) * Kd + k0 + lcol);
            As[lcol + 0][m] = av.x; As[lcol + 1][m] = av.y;
            As[lcol + 2][m] = av.z; As[lcol + 3][m] = av.w;
        }
#pragma unroll
        for (int r = 0; r < 2; r++) {
            int n = lrow + r * 64;
            int gn = col0 + n;
            float4 bv = make_float4(0.f, 0.f, 0.f, 0.f);
            if (gn < N) bv = *(const float4*)(Bm + (size_t)gn * Kd + k0 + lcol);
            Bs[lcol + 0][n] = bv.x; Bs[lcol + 1][n] = bv.y;
            Bs[lcol + 2][n] = bv.z; Bs[lcol + 3][n] = bv.w;
        }
        __syncthreads();
#pragma unroll
        for (int k = 0; k < BK; k++) {
            float a[TM], b[TN];
#pragma unroll
            for (int i = 0; i < TM; i++) a[i] = As[k][ty * TM + i];
#pragma unroll
            for (int j = 0; j < TN; j++) b[j] = Bs[k][tx * TN + j];
#pragma unroll
            for (int i = 0; i < TM; i++)
#pragma unroll
                for (int j = 0; j < TN; j++) acc[i][j] = fmaf(a[i], b[j], acc[i][j]);
        }
        __syncthreads();
    }

#pragma unroll
    for (int i = 0; i < TM; i++) {
        int m = row0 + ty * TM + i;
#pragma unroll
        for (int j = 0; j < TN; j++) {
            int n = col0 + tx * TN + j;
            if (n < N) {
                float v = acc[i][j];
                if (bias) v += bias[n];
                C[(size_t)m * N + n] = v;
            }
        }
    }
}

// ---------------- quad epilogue: combine S, P into -q or exp(-q/NH) -----------
__global__ void quad_epi(const float* __restrict__ S, const float* __restrict__ P,
                         const float* __restrict__ rsq, const float* __restrict__ msq,
                         const float* __restrict__ c, const float* __restrict__ lam,
                         float* __restrict__ out, int mode) {
    size_t idx = (size_t)blockIdx.x * 256 + threadIdx.x;
    int n = (int)(idx & (NH - 1));
    int b = (int)(idx >> 11);
    float q = lam[n] * (rsq[b] - 2.f * S[idx] + msq[n]);
    float4 p  = *(const float4*)(P + idx * 4);
    float4 cc = *(const float4*)(c + n * 4);
    float d0 = p.x - cc.x, d1 = p.y - cc.y, d2 = p.z - cc.z, d3 = p.w - cc.w;
    q += d0 * d0 + d1 * d1 + d2 * d2 + d3 * d3;
    out[idx] = mode ? expf(-q * (1.0f / (float)NH)) : -q;
}

// ---------------- BatchNorm (training-mode, two-pass variance) ----------------
__global__ void bn_sum_partial(const float* __restrict__ t, float* __restrict__ psum) {
    int n = blockIdx.x * 256 + threadIdx.x;
    int seg = blockIdx.y;
    const int rows = BATCH / NSEG;
    const float* p = t + (size_t)seg * rows * NH + n;
    float s = 0.f;
    for (int r = 0; r < rows; r++) s += p[(size_t)r * NH];
    psum[seg * NH + n] = s;
}
__global__ void bn_mean(const float* __restrict__ psum, float* __restrict__ mean) {
    int n = blockIdx.x * 256 + threadIdx.x;
    float s = 0.f;
    for (int i = 0; i < NSEG; i++) s += psum[i * NH + n];
    mean[n] = s * (1.0f / (float)BATCH);
}
__global__ void bn_var_partial(const float* __restrict__ t, const float* __restrict__ mean,
                               float* __restrict__ psq) {
    int n = blockIdx.x * 256 + threadIdx.x;
    int seg = blockIdx.y;
    const int rows = BATCH / NSEG;
    const float* p = t + (size_t)seg * rows * NH + n;
    float m = mean[n];
    float s = 0.f;
    for (int r = 0; r < rows; r++) { float d = p[(size_t)r * NH] - m; s = fmaf(d, d, s); }
    psq[seg * NH + n] = s;
}
__global__ void bn_finalize(const float* __restrict__ psq, const float* __restrict__ mean,
                            const float* __restrict__ g, const float* __restrict__ be,
                            float* __restrict__ scale, float* __restrict__ shift) {
    int n = blockIdx.x * 256 + threadIdx.x;
    float s = 0.f;
    for (int i = 0; i < NSEG; i++) s += psq[i * NH + n];
    float var = s * (1.0f / (float)BATCH);
    float rstd = rsqrtf(var + BN_EPS);
    float sc = g[n] * rstd;
    scale[n] = sc;
    shift[n] = be[n] - mean[n] * sc;
}
__global__ void bn_apply(const float* __restrict__ t, const float* __restrict__ scale,
                         const float* __restrict__ shift, float* __restrict__ feat,
                         float* o1, float* o2, int relu) {
    size_t idx = (size_t)blockIdx.x * 256 + threadIdx.x;
    int n = (int)(idx & (NH - 1));
    float v = fmaf(t[idx], scale[n], shift[n]);
    if (relu) v = fmaxf(v, 0.f);
    feat[idx] = v;
    if (o1) o1[idx] = v;
    if (o2) o2[idx] = v;
}

// ---------------- host orchestration ----------------
extern "C" void kernel_launch(void* const* d_in, const int* in_sizes, int n_in,
                              void* d_out, int out_size) {
    const float* x    = (const float*)d_in[0];
    const float* mu1  = (const float*)d_in[1];
    const float* lam1 = (const float*)d_in[2];
    const float* v1   = (const float*)d_in[3];
    const float* g1   = (const float*)d_in[4];
    const float* b1   = (const float*)d_in[5];
    const float* mu2  = (const float*)d_in[6];
    const float* lam2 = (const float*)d_in[7];
    const float* v2   = (const float*)d_in[8];
    const float* g2   = (const float*)d_in[9];
    const float* b2   = (const float*)d_in[10];
    const float* Wl   = (const float*)d_in[11];
    const float* bl   = (const float*)d_in[12];

    float *pS, *pP, *pT, *pF, *pR, *pM, *pC, *pMean, *pScale, *pShift, *pPsum, *pPsq;
    cudaGetSymbolAddress((void**)&pS, g_S);
    cudaGetSymbolAddress((void**)&pP, g_P);
    cudaGetSymbolAddress((void**)&pT, g_t);
    cudaGetSymbolAddress((void**)&pF, g_feat);
    cudaGetSymbolAddress((void**)&pR, g_rowsq);
    cudaGetSymbolAddress((void**)&pM, g_msq);
    cudaGetSymbolAddress((void**)&pC, g_c);
    cudaGetSymbolAddress((void**)&pMean, g_mean);
    cudaGetSymbolAddress((void**)&pScale, g_scale);
    cudaGetSymbolAddress((void**)&pShift, g_shift);
    cudaGetSymbolAddress((void**)&pPsum, g_psum);
    cudaGetSymbolAddress((void**)&pPsq, g_psq);

    const size_t LOGITS_SZ = (size_t)BATCH * NCLS;
    const size_t FEAT_SZ   = (size_t)BATCH * NH;
    float* out = (float*)d_out;
    size_t extra = ((size_t)out_size > LOGITS_SZ) ? ((size_t)out_size - LOGITS_SZ) / FEAT_SZ : 0;
    float* f1dst = (extra >= 1) ? out + LOGITS_SZ : nullptr;
    float* f2a   = (extra >= 2) ? out + LOGITS_SZ + FEAT_SZ : nullptr;
    float* f2b   = (extra >= 3) ? out + LOGITS_SZ + 2 * FEAT_SZ : nullptr;

    dim3 bn_grid(NH / 256, NSEG);
    int elem_blocks = (int)(((size_t)BATCH * NH) / 256);

    // ---------- Layer 1 ----------
    rowsq_kernel<<<BATCH, 256>>>(x, pR, D_IN);
    prep_kernel<<<NH, 256>>>(mu1, v1, pM, pC, D_IN);
    sgemm_nt<<<dim3(NH / BN, BATCH / BM), 256>>>(x, mu1, pS, BATCH, NH, D_IN, nullptr);
    sgemm_nt<<<dim3((NH * KLR) / BN, BATCH / BM), 256>>>(x, v1, pP, BATCH, NH * KLR, D_IN, nullptr);
    quad_epi<<<elem_blocks, 256>>>(pS, pP, pR, pM, pC, lam1, pT, 0);
    bn_sum_partial<<<bn_grid, 256>>>(pT, pPsum);
    bn_mean<<<NH / 256, 256>>>(pPsum, pMean);
    bn_var_partial<<<bn_grid, 256>>>(pT, pMean, pPsq);
    bn_finalize<<<NH / 256, 256>>>(pPsq, pMean, g1, b1, pScale, pShift);
    bn_apply<<<elem_blocks, 256>>>(pT, pScale, pShift, pF, f1dst, nullptr, 0);

    // ---------- Layer 2 ----------
    rowsq_kernel<<<BATCH, 256>>>(pF, pR, NH);
    prep_kernel<<<NH, 256>>>(mu2, v2, pM, pC, NH);
    sgemm_nt<<<dim3(NH / BN, BATCH / BM), 256>>>(pF, mu2, pS, BATCH, NH, NH, nullptr);
    sgemm_nt<<<dim3((NH * KLR) / BN, BATCH / BM), 256>>>(pF, v2, pP, BATCH, NH * KLR, NH, nullptr);
    quad_epi<<<elem_blocks, 256>>>(pS, pP, pR, pM, pC, lam2, pT, 1);
    bn_sum_partial<<<bn_grid, 256>>>(pT, pPsum);
    bn_mean<<<NH / 256, 256>>>(pPsum, pMean);
    bn_var_partial<<<bn_grid, 256>>>(pT, pMean, pPsq);
    bn_finalize<<<NH / 256, 256>>>(pPsq, pMean, g2, b2, pScale, pShift);
    bn_apply<<<elem_blocks, 256>>>(pT, pScale, pShift, pF, f2a, f2b, 1);

    // ---------- Logits ----------
    sgemm_nt<<<dim3((NCLS + BN - 1) / BN, BATCH / BM), 256>>>(pF, Wl, out, BATCH, NCLS, NH, bl);
}

// round 3
// speedup vs baseline: 2.9910x; 2.9910x over previous
#include <cuda_runtime.h>
#include <cuda_bf16.h>
#include <cstdint>

// Problem constants
#define BATCH 8192
#define D_IN  1024
#define NH    2048
#define KLR   4
#define NCLS  1000
#define BN_EPS 1e-5f
#define NSEG  32

#define STAGES 3
#define STAGE_BYTES 32768           // A 16KB | B 16KB  (128 rows x 128B, bf16 BK=64)
#define SMEM_TOTAL (STAGES * STAGE_BYTES)

static __device__ __forceinline__ uint32_t smem_u32(const void* p) {
    uint32_t a;
    asm("{ .reg .u64 t; cvta.to.shared.u64 t, %1; cvt.u32.u64 %0, t; }" : "=r"(a) : "l"(p));
    return a;
}
static __device__ __forceinline__ void cp16(uint32_t dst, const void* src, uint32_t bytes) {
    asm volatile("cp.async.cg.shared.global [%0], [%1], 16, %2;" :: "r"(dst), "l"(src), "r"(bytes) : "memory");
}
#define CP_COMMIT() asm volatile("cp.async.commit_group;" ::: "memory")
#define CP_WAIT(n)  asm volatile("cp.async.wait_group %0;" :: "n"(n) : "memory")
#define LDSM4(r0, r1, r2, r3, a) \
    asm volatile("ldmatrix.sync.aligned.m8n8.x4.shared.b16 {%0,%1,%2,%3}, [%4];" \
        : "=r"(r0), "=r"(r1), "=r"(r2), "=r"(r3) : "r"(a))
#define MMA16816(c, a, b0, b1) \
    asm volatile("mma.sync.aligned.m16n8k16.row.col.f32.bf16.bf16.f32 " \
        "{%0,%1,%2,%3},{%4,%5,%6,%7},{%8,%9},{%0,%1,%2,%3};" \
        : "+f"((c)[0]), "+f"((c)[1]), "+f"((c)[2]), "+f"((c)[3]) \
        : "r"((a)[0]), "r"((a)[1]), "r"((a)[2]), "r"((a)[3]), "r"(b0), "r"(b1))

// ---------------- static device scratch ----------------
__device__ float g_S[(size_t)BATCH * NH];
__device__ float g_P[(size_t)BATCH * NH * KLR];
__device__ float g_t[(size_t)BATCH * NH];
__device__ float g_feat[(size_t)BATCH * NH];
__device__ __align__(1024) __nv_bfloat16 g_a3x[(size_t)BATCH * 3 * D_IN];    // x  split-A
__device__ __align__(1024) __nv_bfloat16 g_a3f[(size_t)BATCH * 3 * NH];      // feat split-A
__device__ __align__(1024) __nv_bfloat16 g_b3mu[(size_t)NH * 3 * NH];        // mu split-B
__device__ __align__(1024) __nv_bfloat16 g_b3v[(size_t)BATCH * 3 * NH];      // v  split-B (NH*KLR=8192 rows)
__device__ __align__(1024) __nv_bfloat16 g_b3l[(size_t)NCLS * 3 * NH];       // Wl split-B
__device__ float g_rowsq[BATCH];
__device__ float g_msq[NH];
__device__ float g_c[NH * KLR];
__device__ float g_mean[NH];
__device__ float g_scale[NH];
__device__ float g_shift[NH];
__device__ float g_psum[NSEG * NH];
__device__ float g_psq[NSEG * NH];

// ================= HMMA bf16 split GEMM =================
// C[m,n] = sum_d A3[m,d]*B3[n,d] (+bias) over concatenated Kd3 = 3*Kd.
// A3: (M, Kd3) row-major bf16, B3: (N, Kd3) row-major bf16. M % 128 == 0.
__global__ void __launch_bounds__(256)
gemm_mma(const __nv_bfloat16* __restrict__ A3, const __nv_bfloat16* __restrict__ B3,
         float* __restrict__ C, int Mt, int N, int Kd3, const float* __restrict__ bias)
{
    extern __shared__ __align__(1024) char smem[];
    const uint32_t sbase = smem_u32(smem);
    const int tid = threadIdx.x;
    const int wid = tid >> 5;
    const int lane = tid & 31;
    const int wm = wid >> 2;          // 0..1  (m-warp, 64 rows)
    const int wn = wid & 3;           // 0..3  (n-warp, 32 cols)

    // banded raster: 8 n-tiles per band across all m-tiles (L2 reuse)
    const int bw = Mt * 8;
    const int band = blockIdx.x / bw;
    const int rr = blockIdx.x % bw;
    const int mtile = rr >> 3;
    const int ntile = band * 8 + (rr & 7);
    const int row0 = mtile * 128;
    const int col0 = ntile * 128;
    const int nk = Kd3 >> 6;

    float acc[4][4][4];
#pragma unroll
    for (int i = 0; i < 4; i++)
#pragma unroll
        for (int j = 0; j < 4; j++)
#pragma unroll
            for (int r = 0; r < 4; r++) acc[i][j][r] = 0.f;

    // per-thread load geometry: 8 chunks of 16B per stage per operand-pair
    // ids 0..1023 per operand: row = id/8 (0..127), c = id%8 (16B column)
    // ldmatrix lane geometry
    const int aRow = wm * 64 + (lane & 15);
    const int aK8 = (lane >> 4) * 8;
    const int bRow = wn * 32 + (lane & 7) + ((lane >> 4) & 1) * 8;
    const int bK8 = ((lane >> 3) & 1) * 8;

    // ---- pipelined main loop ----
    auto issue = [&](int i) {
        if (i < nk) {
            const int s = i % STAGES;
            const uint32_t stA = sbase + s * STAGE_BYTES;
            const uint32_t stB = stA + 16384;
            const int k0 = i << 6;
#pragma unroll
            for (int it = 0; it < 4; it++) {
                int id = it * 256 + tid;
                int row = id >> 3, c = id & 7;
                uint32_t off = (uint32_t)(row * 128 + ((c * 16) ^ ((row & 7) << 4)));
                cp16(stA + off, A3 + (size_t)(row0 + row) * Kd3 + k0 + c * 8, 16);
            }
#pragma unroll
            for (int it = 0; it < 4; it++) {
                int id = it * 256 + tid;
                int row = id >> 3, c = id & 7;
                int gn = col0 + row;
                uint32_t bytes = (gn < N) ? 16u : 0u;
                if (gn >= N) gn = col0;
                uint32_t off = (uint32_t)(row * 128 + ((c * 16) ^ ((row & 7) << 4)));
                cp16(stB + off, B3 + (size_t)gn * Kd3 + k0 + c * 8, bytes);
            }
        }
        CP_COMMIT();
    };

#pragma unroll
    for (int i = 0; i < STAGES - 1; i++) issue(i);

    for (int i = 0; i < nk; i++) {
        CP_WAIT(STAGES - 2);
        __syncthreads();
        const int s = i % STAGES;
        const uint32_t stA = sbase + s * STAGE_BYTES;
        const uint32_t stB = stA + 16384;
#pragma unroll
        for (int ks = 0; ks < 4; ks++) {
            uint32_t a[4][4], b[2][4];
            const int kc = ks * 16;
#pragma unroll
            for (int mi = 0; mi < 4; mi++) {
                int row = aRow + mi * 16;
                uint32_t off = (uint32_t)(row * 128 + (((kc + aK8) * 2) ^ ((row & 7) << 4)));
                LDSM4(a[mi][0], a[mi][1], a[mi][2], a[mi][3], stA + off);
            }
#pragma unroll
            for (int nb = 0; nb < 2; nb++) {
                int row = bRow + nb * 16;
                uint32_t off = (uint32_t)(row * 128 + (((kc + bK8) * 2) ^ ((row & 7) << 4)));
                LDSM4(b[nb][0], b[nb][1], b[nb][2], b[nb][3], stB + off);
            }
#pragma unroll
            for (int mi = 0; mi < 4; mi++)
#pragma unroll
                for (int ni = 0; ni < 4; ni++)
                    MMA16816(acc[mi][ni], a[mi], b[ni >> 1][(ni & 1) * 2], b[ni >> 1][(ni & 1) * 2 + 1]);
        }
        issue(i + STAGES - 1);
    }

    // ---- epilogue ----
#pragma unroll
    for (int mi = 0; mi < 4; mi++) {
        const int m = row0 + wm * 64 + mi * 16 + (lane >> 2);
#pragma unroll
        for (int ni = 0; ni < 4; ni++) {
            const int col = col0 + wn * 32 + ni * 8 + (lane & 3) * 2;
            if (col < N) {
                float b0 = 0.f, b1 = 0.f;
                if (bias) { b0 = bias[col]; b1 = bias[col + 1]; }
                float2 v0 = make_float2(acc[mi][ni][0] + b0, acc[mi][ni][1] + b1);
                float2 v1 = make_float2(acc[mi][ni][2] + b0, acc[mi][ni][3] + b1);
                *(float2*)(C + (size_t)m * N + col) = v0;
                *(float2*)(C + (size_t)(m + 8) * N + col) = v1;
            }
        }
    }
}

// ---------------- splits: fp32 -> concatenated bf16 triples ----------------
// A-layout: [hi | lo | hi], B-layout: [hi | hi | lo]
__global__ void split_A(const float* __restrict__ src, __nv_bfloat16* __restrict__ dst, int D) {
    size_t i = (size_t)blockIdx.x * 256 + threadIdx.x;
    size_t r = i / (size_t)D;
    int d = (int)(i - r * D);
    float x = src[i];
    __nv_bfloat16 h = __float2bfloat16(x);
    __nv_bfloat16 l = __float2bfloat16(x - __bfloat162float(h));
    __nv_bfloat16* o = dst + r * (size_t)(3 * D);
    o[d] = h; o[D + d] = l; o[2 * D + d] = h;
}
__global__ void split_B(const float* __restrict__ src, __nv_bfloat16* __restrict__ dst, int D) {
    size_t i = (size_t)blockIdx.x * 256 + threadIdx.x;
    size_t r = i / (size_t)D;
    int d = (int)(i - r * D);
    float x = src[i];
    __nv_bfloat16 h = __float2bfloat16(x);
    __nv_bfloat16 l = __float2bfloat16(x - __bfloat162float(h));
    __nv_bfloat16* o = dst + r * (size_t)(3 * D);
    o[d] = h; o[D + d] = h; o[2 * D + d] = l;
}

// ---------------- row sum of squares ----------------
__global__ void rowsq_kernel(const float* __restrict__ x, float* __restrict__ out, int D) {
    int b = blockIdx.x;
    const float* p = x + (size_t)b * D;
    float s = 0.f;
    for (int i = threadIdx.x; i < D; i += 256) { float v = p[i]; s = fmaf(v, v, s); }
    __shared__ float red[256];
    red[threadIdx.x] = s;
    __syncthreads();
    for (int off = 128; off > 0; off >>= 1) {
        if (threadIdx.x < off) red[threadIdx.x] += red[threadIdx.x + off];
        __syncthreads();
    }
    if (threadIdx.x == 0) out[b] = red[0];
}

// ---------------- per-n constants: msq, c ----------------
__global__ void prep_kernel(const float* __restrict__ mu, const float* __restrict__ v,
                            float* __restrict__ msq, float* __restrict__ c, int D) {
    int n = blockIdx.x;
    const float* mp = mu + (size_t)n * D;
    const float* vp = v + (size_t)n * KLR * D;
    float acc[5] = {0.f, 0.f, 0.f, 0.f, 0.f};
    for (int i = threadIdx.x; i < D; i += 256) {
        float m = mp[i];
        acc[0] = fmaf(m, m, acc[0]);
        acc[1] = fmaf(m, vp[i], acc[1]);
        acc[2] = fmaf(m, vp[(size_t)D + i], acc[2]);
        acc[3] = fmaf(m, vp[(size_t)2 * D + i], acc[3]);
        acc[4] = fmaf(m, vp[(size_t)3 * D + i], acc[4]);
    }
    __shared__ float red[256];
    for (int j = 0; j < 5; j++) {
        red[threadIdx.x] = acc[j];
        __syncthreads();
        for (int off = 128; off > 0; off >>= 1) {
            if (threadIdx.x < off) red[threadIdx.x] += red[threadIdx.x + off];
            __syncthreads();
        }
        if (threadIdx.x == 0) {
            if (j == 0) msq[n] = red[0];
            else        c[n * KLR + (j - 1)] = red[0];
        }
        __syncthreads();
    }
}

// ---------------- quad epilogue ----------------
__global__ void quad_epi(const float* __restrict__ S, const float* __restrict__ P,
                         const float* __restrict__ rsq, const float* __restrict__ msq,
                         const float* __restrict__ c, const float* __restrict__ lam,
                         float* __restrict__ out, int mode) {
    size_t idx = (size_t)blockIdx.x * 256 + threadIdx.x;
    int n = (int)(idx & (NH - 1));
    int b = (int)(idx >> 11);
    float q = lam[n] * (rsq[b] - 2.f * S[idx] + msq[n]);
    float4 p  = *(const float4*)(P + idx * 4);
    float4 cc = *(const float4*)(c + n * 4);
    float d0 = p.x - cc.x, d1 = p.y - cc.y, d2 = p.z - cc.z, d3 = p.w - cc.w;
    q += d0 * d0 + d1 * d1 + d2 * d2 + d3 * d3;
    out[idx] = mode ? expf(-q * (1.0f / (float)NH)) : -q;
}

// ---------------- BatchNorm (two-pass variance) ----------------
__global__ void bn_sum_partial(const float* __restrict__ t, float* __restrict__ psum) {
    int n = blockIdx.x * 256 + threadIdx.x;
    int seg = blockIdx.y;
    const int rows = BATCH / NSEG;
    const float* p = t + (size_t)seg * rows * NH + n;
    float s = 0.f;
    for (int r = 0; r < rows; r++) s += p[(size_t)r * NH];
    psum[seg * NH + n] = s;
}
__global__ void bn_mean(const float* __restrict__ psum, float* __restrict__ mean) {
    int n = blockIdx.x * 256 + threadIdx.x;
    float s = 0.f;
    for (int i = 0; i < NSEG; i++) s += psum[i * NH + n];
    mean[n] = s * (1.0f / (float)BATCH);
}
__global__ void bn_var_partial(const float* __restrict__ t, const float* __restrict__ mean,
                               float* __restrict__ psq) {
    int n = blockIdx.x * 256 + threadIdx.x;
    int seg = blockIdx.y;
    const int rows = BATCH / NSEG;
    const float* p = t + (size_t)seg * rows * NH + n;
    float m = mean[n];
    float s = 0.f;
    for (int r = 0; r < rows; r++) { float d = p[(size_t)r * NH] - m; s = fmaf(d, d, s); }
    psq[seg * NH + n] = s;
}
__global__ void bn_finalize(const float* __restrict__ psq, const float* __restrict__ mean,
                            const float* __restrict__ g, const float* __restrict__ be,
                            float* __restrict__ scale, float* __restrict__ shift) {
    int n = blockIdx.x * 256 + threadIdx.x;
    float s = 0.f;
    for (int i = 0; i < NSEG; i++) s += psq[i * NH + n];
    float var = s * (1.0f / (float)BATCH);
    float rstd = rsqrtf(var + BN_EPS);
    float sc = g[n] * rstd;
    scale[n] = sc;
    shift[n] = be[n] - mean[n] * sc;
}
// applies BN (+optional relu), writes float feat AND split-A bf16 triple
__global__ void bn_apply(const float* __restrict__ t, const float* __restrict__ scale,
                         const float* __restrict__ shift, float* __restrict__ feat,
                         __nv_bfloat16* __restrict__ f3,
                         float* o1, float* o2, int relu) {
    size_t idx = (size_t)blockIdx.x * 256 + threadIdx.x;
    int n = (int)(idx & (NH - 1));
    size_t b = idx >> 11;
    float v = fmaf(t[idx], scale[n], shift[n]);
    if (relu) v = fmaxf(v, 0.f);
    feat[idx] = v;
    __nv_bfloat16 h = __float2bfloat16(v);
    __nv_bfloat16 l = __float2bfloat16(v - __bfloat162float(h));
    __nv_bfloat16* o = f3 + b * (size_t)(3 * NH);
    o[n] = h; o[NH + n] = l; o[2 * NH + n] = h;
    if (o1) o1[idx] = v;
    if (o2) o2[idx] = v;
}

// ---------------- host orchestration ----------------
extern "C" void kernel_launch(void* const* d_in, const int* in_sizes, int n_in,
                              void* d_out, int out_size) {
    const float* x    = (const float*)d_in[0];
    const float* mu1  = (const float*)d_in[1];
    const float* lam1 = (const float*)d_in[2];
    const float* v1   = (const float*)d_in[3];
    const float* g1   = (const float*)d_in[4];
    const float* b1   = (const float*)d_in[5];
    const float* mu2  = (const float*)d_in[6];
    const float* lam2 = (const float*)d_in[7];
    const float* v2   = (const float*)d_in[8];
    const float* g2   = (const float*)d_in[9];
    const float* b2   = (const float*)d_in[10];
    const float* Wl   = (const float*)d_in[11];
    const float* bl   = (const float*)d_in[12];

    float *pS, *pP, *pT, *pF, *pR, *pM, *pC, *pMean, *pScale, *pShift, *pPsum, *pPsq;
    __nv_bfloat16 *pA3x, *pA3f, *pB3mu, *pB3v, *pB3l;
    cudaGetSymbolAddress((void**)&pS, g_S);
    cudaGetSymbolAddress((void**)&pP, g_P);
    cudaGetSymbolAddress((void**)&pT, g_t);
    cudaGetSymbolAddress((void**)&pF, g_feat);
    cudaGetSymbolAddress((void**)&pA3x, g_a3x);
    cudaGetSymbolAddress((void**)&pA3f, g_a3f);
    cudaGetSymbolAddress((void**)&pB3mu, g_b3mu);
    cudaGetSymbolAddress((void**)&pB3v, g_b3v);
    cudaGetSymbolAddress((void**)&pB3l, g_b3l);
    cudaGetSymbolAddress((void**)&pR, g_rowsq);
    cudaGetSymbolAddress((void**)&pM, g_msq);
    cudaGetSymbolAddress((void**)&pC, g_c);
    cudaGetSymbolAddress((void**)&pMean, g_mean);
    cudaGetSymbolAddress((void**)&pScale, g_scale);
    cudaGetSymbolAddress((void**)&pShift, g_shift);
    cudaGetSymbolAddress((void**)&pPsum, g_psum);
    cudaGetSymbolAddress((void**)&pPsq, g_psq);

    cudaFuncSetAttribute(gemm_mma, cudaFuncAttributeMaxDynamicSharedMemorySize, SMEM_TOTAL);

    const size_t LOGITS_SZ = (size_t)BATCH * NCLS;
    const size_t FEAT_SZ   = (size_t)BATCH * NH;
    float* out = (float*)d_out;
    size_t extra = ((size_t)out_size > LOGITS_SZ) ? ((size_t)out_size - LOGITS_SZ) / FEAT_SZ : 0;
    float* f1dst = (extra >= 1) ? out + LOGITS_SZ : nullptr;
    float* f2a   = (extra >= 2) ? out + LOGITS_SZ + FEAT_SZ : nullptr;
    float* f2b   = (extra >= 3) ? out + LOGITS_SZ + 2 * FEAT_SZ : nullptr;

    dim3 bn_grid(NH / 256, NSEG);
    const int elem_blocks = (int)(((size_t)BATCH * NH) / 256);
    const int Mt = BATCH / 128;   // 64

    // ---------- Layer 1 ----------
    split_A<<<(BATCH * D_IN) / 256, 256>>>(x, pA3x, D_IN);
    split_B<<<(NH * D_IN) / 256, 256>>>(mu1, pB3mu, D_IN);
    split_B<<<(NH * KLR * D_IN) / 256, 256>>>(v1, pB3v, D_IN);
    rowsq_kernel<<<BATCH, 256>>>(x, pR, D_IN);
    prep_kernel<<<NH, 256>>>(mu1, v1, pM, pC, D_IN);
    gemm_mma<<<Mt * (NH / 128), 256, SMEM_TOTAL>>>(pA3x, pB3mu, pS, Mt, NH, 3 * D_IN, nullptr);
    gemm_mma<<<Mt * ((NH * KLR) / 128), 256, SMEM_TOTAL>>>(pA3x, pB3v, pP, Mt, NH * KLR, 3 * D_IN, nullptr);
    quad_epi<<<elem_blocks, 256>>>(pS, pP, pR, pM, pC, lam1, pT, 0);
    bn_sum_partial<<<bn_grid, 256>>>(pT, pPsum);
    bn_mean<<<NH / 256, 256>>>(pPsum, pMean);
    bn_var_partial<<<bn_grid, 256>>>(pT, pMean, pPsq);
    bn_finalize<<<NH / 256, 256>>>(pPsq, pMean, g1, b1, pScale, pShift);
    bn_apply<<<elem_blocks, 256>>>(pT, pScale, pShift, pF, pA3f, f1dst, nullptr, 0);

    // ---------- Layer 2 ----------
    split_B<<<(NH * NH) / 256, 256>>>(mu2, pB3mu, NH);
    split_B<<<(NH * KLR * NH) / 256, 256>>>(v2, pB3v, NH);
    rowsq_kernel<<<BATCH, 256>>>(pF, pR, NH);
    prep_kernel<<<NH, 256>>>(mu2, v2, pM, pC, NH);
    gemm_mma<<<Mt * (NH / 128), 256, SMEM_TOTAL>>>(pA3f, pB3mu, pS, Mt, NH, 3 * NH, nullptr);
    gemm_mma<<<Mt * ((NH * KLR) / 128), 256, SMEM_TOTAL>>>(pA3f, pB3v, pP, Mt, NH * KLR, 3 * NH, nullptr);
    quad_epi<<<elem_blocks, 256>>>(pS, pP, pR, pM, pC, lam2, pT, 1);
    bn_sum_partial<<<bn_grid, 256>>>(pT, pPsum);
    bn_mean<<<NH / 256, 256>>>(pPsum, pMean);
    bn_var_partial<<<bn_grid, 256>>>(pT, pMean, pPsq);
    bn_finalize<<<NH / 256, 256>>>(pPsq, pMean, g2, b2, pScale, pShift);
    bn_apply<<<elem_blocks, 256>>>(pT, pScale, pShift, pF, pA3f, f2a, f2b, 1);

    // ---------- Logits ----------
    split_B<<<(NCLS * NH) / 256, 256>>>(Wl, pB3l, NH);
    gemm_mma<<<Mt * 8, 256, SMEM_TOTAL>>>(pA3f, pB3l, out, Mt, NCLS, 3 * NH, bl);
}